// round 14
// baseline (speedup 1.0000x reference)
#include <cuda_runtime.h>
#include <cuda_fp16.h>
#include <math_constants.h>
#include <stdint.h>

#define N_ROWS 4096
#define DIM    144
#define KCODES 50257
#define NT160  315
#define KPADC  (NT160 * 160)         // 50400
#define KP     152                   // padded f16 row width (304 bytes)
#define NT32   (NT160 * 5)           // 1575
#define ITEMS  (16 * NT160)          // 5040
#define NBLK   148
#define ZQ_ELEMS (N_ROWS * DIM)
#define EFW    (NT160 * 32)          // 10080 floats per d-row of g_ef

#define ESCALE 16384.0f              // 2^14 exact
#define DCOEF  (-1.220703125e-4f)    // -2 * 2^-14 exact

// smem: A 256x304 | B x2 128x304 | EF x2 144x128B | ens x2 160 floats
#define OFF_B   77824
#define BBUF    38912
#define OFF_EF  155648
#define EFBUF   18432
#define OFF_ENS 192512
#define SMEM_GM 193792

// ---- scratch ----
__device__ float   g_zn[N_ROWS];
__device__ float   g_en[KPADC];
__device__ __half  g_zh[(size_t)N_ROWS * KP];
__device__ __half  g_eh[(size_t)KPADC * KP];
__device__ float   g_ef[(size_t)DIM * EFW];      // [d][item*32+j] fp32 FMA-path e
__device__ float   g_tmin[(size_t)NT32 * N_ROWS];
__device__ double  g_rowloss[N_ROWS];

__device__ __forceinline__ uint32_t smem_u32(const void* p) {
    uint32_t a;
    asm("{ .reg .u64 t; cvta.to.shared.u64 t, %1; cvt.u32.u64 %0, t; }" : "=r"(a) : "l"(p));
    return a;
}
#define CP_ASYNC16(dst, src) \
    asm volatile("cp.async.cg.shared.global [%0], [%1], 16;" :: "r"(dst), "l"(src) : "memory")
#define CP_COMMIT() asm volatile("cp.async.commit_group;" ::: "memory")
#define CP_WAIT1()  asm volatile("cp.async.wait_group 1;" ::: "memory")
#define LDM4(r, addr) \
    asm volatile("ldmatrix.sync.aligned.m8n8.x4.shared.b16 {%0,%1,%2,%3}, [%4];" \
        : "=r"((r)[0]), "=r"((r)[1]), "=r"((r)[2]), "=r"((r)[3]) : "r"(addr))

__device__ __forceinline__ void mma_f16(uint32_t* c, const uint32_t* a, const uint32_t* b)
{
    asm volatile(
        "mma.sync.aligned.m16n8k16.row.col.f16.f16.f16.f16 "
        "{%0,%1}, {%2,%3,%4,%5}, {%6,%7}, {%0,%1};\n"
        : "+r"(c[0]), "+r"(c[1])
        : "r"(a[0]), "r"(a[1]), "r"(a[2]), "r"(a[3]), "r"(b[0]), "r"(b[1]));
}

// ---------------------------------------------------------------------------
// Kernel 1: exact norms (bit-matching NEON order), fp16 copies, FMA-path e.
// ---------------------------------------------------------------------------
__global__ void prep_kernel(const float* __restrict__ z,
                            const float* __restrict__ emb)
{
    int gid = blockIdx.x * blockDim.x + threadIdx.x;
    __half2 zero2 = __floats2half2_rn(0.f, 0.f);

    if (gid < N_ROWS) {
        const float4* p = reinterpret_cast<const float4*>(z + (size_t)gid * DIM);
        __half2* dst = reinterpret_cast<__half2*>(g_zh + (size_t)gid * KP);
        float p0 = 0.f, p1 = 0.f, p2 = 0.f, p3 = 0.f;
        #pragma unroll
        for (int i = 0; i < DIM / 4; ++i) {
            float4 v = p[i];
            p0 = __fmaf_rn(v.x, v.x, p0);
            p1 = __fmaf_rn(v.y, v.y, p1);
            p2 = __fmaf_rn(v.z, v.z, p2);
            p3 = __fmaf_rn(v.w, v.w, p3);
            dst[i * 2 + 0] = __floats2half2_rn(v.x, v.y);
            dst[i * 2 + 1] = __floats2half2_rn(v.z, v.w);
        }
        #pragma unroll
        for (int i = 72; i < KP / 2; ++i) dst[i] = zero2;
        g_zn[gid] = __fadd_rn(__fadd_rn(p0, p1), __fadd_rn(p2, p3));
    }

    if (gid < KPADC) {
        __half2* dst = reinterpret_cast<__half2*>(g_eh + (size_t)gid * KP);
        bool real = gid < KCODES;
        if (real) {
            const float4* p = reinterpret_cast<const float4*>(emb + (size_t)gid * DIM);
            float p0 = 0.f, p1 = 0.f, p2 = 0.f, p3 = 0.f;
            #pragma unroll
            for (int i = 0; i < DIM / 4; ++i) {
                float4 v = p[i];
                p0 = __fmaf_rn(v.x, v.x, p0);
                p1 = __fmaf_rn(v.y, v.y, p1);
                p2 = __fmaf_rn(v.z, v.z, p2);
                p3 = __fmaf_rn(v.w, v.w, p3);
                dst[i * 2 + 0] = __floats2half2_rn(v.x * ESCALE, v.y * ESCALE);
                dst[i * 2 + 1] = __floats2half2_rn(v.z * ESCALE, v.w * ESCALE);
            }
            #pragma unroll
            for (int i = 72; i < KP / 2; ++i) dst[i] = zero2;
            g_en[gid] = __fadd_rn(__fadd_rn(p0, p1), __fadd_rn(p2, p3));
        } else {
            for (int i = 0; i < KP / 2; ++i) dst[i] = zero2;
            g_en[gid] = CUDART_INF_F;
        }
        int rm = gid % 160;
        if (rm >= 128) {   // FMA-path codes: transposed fp32 copy (fp16-rounded)
            float* dstf = g_ef + (size_t)(gid / 160) * 32 + (rm - 128);
            for (int d = 0; d < DIM; ++d)
                dstf[(size_t)d * EFW] =
                    real ? __half2float(__float2half_rn(emb[(size_t)gid * DIM + d])) : 0.f;
        }
    }
}

// ---------------------------------------------------------------------------
// Kernel 2: hybrid persistent filter. Item = 256 rows x 160 codes:
// codes [0,128) HMMA (tensor), [128,160) fp32 FFMA (fma pipe), anti-phase.
// ---------------------------------------------------------------------------
__device__ __forceinline__ void prefetch_item(int ct, int buf, int tid, uint32_t sbase)
{
    const char* src = reinterpret_cast<const char*>(g_eh) + (size_t)(ct * 160) * 304;
    uint32_t dst = sbase + OFF_B + buf * BBUF;
    #pragma unroll 5
    for (int i = tid; i < 2432; i += 256)
        CP_ASYNC16(dst + i * 16, src + (size_t)i * 16);
    const char* srcf = reinterpret_cast<const char*>(g_ef) + (size_t)(ct * 32) * 4;
    uint32_t dstf = sbase + OFF_EF + buf * EFBUF;
    #pragma unroll 3
    for (int i = tid; i < 1152; i += 256) {
        int d = i >> 3, ch = i & 7;
        CP_ASYNC16(dstf + d * 128 + ch * 16, srcf + (size_t)d * (EFW * 4) + ch * 16);
    }
    if (tid < 40)
        CP_ASYNC16(sbase + OFF_ENS + buf * 640 + tid * 16,
                   reinterpret_cast<const char*>(g_en + ct * 160) + tid * 16);
    CP_COMMIT();
}

__device__ __forceinline__ void hmma_body(uint32_t aBase, uint32_t bB, const float* eb,
                                          const float (&znr)[4][2], int lane,
                                          float (&vmin)[2][4][2])
{
    const int q = lane & 3;
    uint32_t c[4][8][2];
    #pragma unroll
    for (int mi = 0; mi < 4; ++mi)
        #pragma unroll
        for (int ni = 0; ni < 8; ++ni) { c[mi][ni][0] = 0u; c[mi][ni][1] = 0u; }

    #pragma unroll
    for (int ks = 0; ks < 9; ++ks) {
        uint32_t b[4][4];
        #pragma unroll
        for (int p = 0; p < 4; ++p) LDM4(b[p], bB + p * (16 * 304) + ks * 32);
        #pragma unroll
        for (int mi = 0; mi < 4; ++mi) {
            uint32_t a[4];
            LDM4(a, aBase + mi * (16 * 304) + ks * 32);
            #pragma unroll
            for (int p = 0; p < 4; ++p) {
                mma_f16(c[mi][2 * p + 0], a, &b[p][0]);
                mma_f16(c[mi][2 * p + 1], a, &b[p][2]);
            }
        }
    }

    #pragma unroll
    for (int h = 0; h < 2; ++h)
        #pragma unroll
        for (int mi = 0; mi < 4; ++mi)
            { vmin[h][mi][0] = CUDART_INF_F; vmin[h][mi][1] = CUDART_INF_F; }

    #pragma unroll
    for (int ni = 0; ni < 8; ++ni) {
        const int noff = (ni >> 1) * 16 + (ni & 1) * 8;
        const int h = ni >> 2;               // 32-code sub-tile
        float2 e = *reinterpret_cast<const float2*>(eb + noff + q * 2);
        #pragma unroll
        for (int mi = 0; mi < 4; ++mi) {
            float2 lo = __half22float2(*reinterpret_cast<const __half2*>(&c[mi][ni][0]));
            float2 hi = __half22float2(*reinterpret_cast<const __half2*>(&c[mi][ni][1]));
            vmin[h][mi][0] = fminf(vmin[h][mi][0], __fmaf_rn(lo.x, DCOEF, znr[mi][0] + e.x));
            vmin[h][mi][0] = fminf(vmin[h][mi][0], __fmaf_rn(lo.y, DCOEF, znr[mi][0] + e.y));
            vmin[h][mi][1] = fminf(vmin[h][mi][1], __fmaf_rn(hi.x, DCOEF, znr[mi][1] + e.x));
            vmin[h][mi][1] = fminf(vmin[h][mi][1], __fmaf_rn(hi.y, DCOEF, znr[mi][1] + e.y));
        }
    }
    #pragma unroll
    for (int h = 0; h < 2; ++h)
        #pragma unroll
        for (int mi = 0; mi < 4; ++mi)
            #pragma unroll
            for (int rh = 0; rh < 2; ++rh) {
                float v = vmin[h][mi][rh];
                v = fminf(v, __shfl_xor_sync(0xffffffffu, v, 1));
                v = fminf(v, __shfl_xor_sync(0xffffffffu, v, 2));
                vmin[h][mi][rh] = v;
            }
}

// fp32 FFMA path: this thread's row x 32 extra codes.
__device__ __forceinline__ float fma_body(const char* zrow, const float* ef,
                                          const float* ens, float znF)
{
    float acc[32];
    #pragma unroll
    for (int j = 0; j < 32; ++j) acc[j] = 0.f;
    #pragma unroll 2
    for (int dc = 0; dc < 18; ++dc) {
        uint4 zv = *reinterpret_cast<const uint4*>(zrow + dc * 16);
        const __half2* zh = reinterpret_cast<const __half2*>(&zv);
        float zf[8];
        #pragma unroll
        for (int u = 0; u < 4; ++u) {
            float2 f = __half22float2(zh[u]);
            zf[2 * u] = f.x; zf[2 * u + 1] = f.y;
        }
        #pragma unroll
        for (int dd = 0; dd < 8; ++dd) {
            const float4* ep = reinterpret_cast<const float4*>(ef + (dc * 8 + dd) * 32);
            #pragma unroll
            for (int c4 = 0; c4 < 8; ++c4) {
                float4 e = ep[c4];
                acc[c4 * 4 + 0] = __fmaf_rn(zf[dd], e.x, acc[c4 * 4 + 0]);
                acc[c4 * 4 + 1] = __fmaf_rn(zf[dd], e.y, acc[c4 * 4 + 1]);
                acc[c4 * 4 + 2] = __fmaf_rn(zf[dd], e.z, acc[c4 * 4 + 2]);
                acc[c4 * 4 + 3] = __fmaf_rn(zf[dd], e.w, acc[c4 * 4 + 3]);
            }
        }
    }
    float vF = CUDART_INF_F;
    #pragma unroll
    for (int j = 0; j < 32; ++j)
        vF = fminf(vF, __fmaf_rn(acc[j], -2.f, znF + ens[128 + j]));
    return vF;
}

__global__ void __launch_bounds__(256, 1) gemm_kernel()
{
    extern __shared__ char sm[];
    const int tid  = threadIdx.x;
    const int lane = tid & 31;
    const int wid  = tid >> 5;
    const int wm   = wid >> 1;
    const int wn   = wid & 1;
    const uint32_t sbase = smem_u32(sm);

    const int aRow = (lane & 7) + ((lane >> 3) & 1) * 8;
    const int aK16 = lane >> 4;
    const int bRow = (lane & 7) + (lane >> 4) * 8;
    const int bK16 = (lane >> 3) & 1;
    const uint32_t aBase  = sbase + (uint32_t)(wm * 64 + aRow) * 304 + aK16 * 16;
    const uint32_t bBase0 = sbase + OFF_B + (uint32_t)(wn * 64 + bRow) * 304 + bK16 * 16;
    const int rowF = tid;   // FMA path: one row per thread

    const int per = ITEMS / NBLK;                 // 34
    const int rem = ITEMS - per * NBLK;           // 8
    int it = blockIdx.x * per + min((int)blockIdx.x, rem);
    const int iend = it + per + (blockIdx.x < rem ? 1 : 0);

    prefetch_item(it % NT160, it & 1, tid, sbase);

    int cur_rb = -1;
    float znr[4][2], znF = 0.f;

    for (; it < iend; ++it) {
        const int rb = it / NT160;
        const int ct = it - rb * NT160;
        if (it + 1 < iend) prefetch_item((it + 1) % NT160, (it + 1) & 1, tid, sbase);
        else               CP_COMMIT();

        if (rb != cur_rb) {
            cur_rb = rb;
            const uint4* src = reinterpret_cast<const uint4*>(g_zh + (size_t)rb * 256 * KP);
            uint4* dst = reinterpret_cast<uint4*>(sm);
            #pragma unroll 4
            for (int i = tid; i < 4864; i += 256) dst[i] = src[i];
            #pragma unroll
            for (int mi = 0; mi < 4; ++mi)
                #pragma unroll
                for (int rh = 0; rh < 2; ++rh)
                    znr[mi][rh] = g_zn[rb * 256 + wm * 64 + mi * 16 + rh * 8 + (lane >> 2)];
            znF = g_zn[rb * 256 + rowF];
        }

        CP_WAIT1();
        __syncthreads();

        const int buf = it & 1;
        const uint32_t bB = bBase0 + buf * BBUF;
        const float* ens = reinterpret_cast<const float*>(sm + OFF_ENS + buf * 640);
        const float* ef  = reinterpret_cast<const float*>(sm + OFF_EF + buf * EFBUF);

        float vmin[2][4][2], vF;
        if (wid & 1) {
            vF = fma_body(sm + rowF * 304, ef, ens, znF);
            hmma_body(aBase, bB, ens + wn * 64, znr, lane, vmin);
        } else {
            hmma_body(aBase, bB, ens + wn * 64, znr, lane, vmin);
            vF = fma_body(sm + rowF * 304, ef, ens, znF);
        }

        const int rowbase = rb * 256;
        if ((lane & 3) == 0) {
            #pragma unroll
            for (int h = 0; h < 2; ++h) {
                const size_t base = (size_t)(5 * ct + wn * 2 + h) * N_ROWS
                                  + rowbase + wm * 64;
                #pragma unroll
                for (int mi = 0; mi < 4; ++mi)
                    #pragma unroll
                    for (int rh = 0; rh < 2; ++rh)
                        g_tmin[base + mi * 16 + rh * 8 + (lane >> 2)] = vmin[h][mi][rh];
            }
        }
        g_tmin[(size_t)(5 * ct + 4) * N_ROWS + rowbase + rowF] = vF;
        __syncthreads();
    }
}

// ---------------------------------------------------------------------------
// Kernel 3: exact rescore over 32-wide tiles, per-type margins, two-sided
// criterion: keep tile i iff tmin_i - m_i <= min_j (tmin_j + m_j).
// ---------------------------------------------------------------------------
__global__ void __launch_bounds__(128) rescore_kernel(const float* __restrict__ z,
                                                      const float* __restrict__ emb,
                                                      float* __restrict__ out)
{
    __shared__ float  zs[DIM];
    __shared__ float  smin[128];
    __shared__ int    list[64];
    __shared__ int    cnt;
    __shared__ float  stage[32 * 145];
    __shared__ float  rbv[128];
    __shared__ int    rbi[128];
    __shared__ double dred[128];

    const int row = blockIdx.x;
    const int tid = threadIdx.x;
    const float zn = g_zn[row];
    const float mH = 2e-5f + 2.2e-6f * sqrtf(zn);
    const float mF = 5e-6f + 5e-7f * sqrtf(zn);

    float tv[13]; int ti[13]; int nl = 0;
    float mloc = CUDART_INF_F;
    for (int i = tid; i < NT32; i += 128) {
        float v = g_tmin[(size_t)i * N_ROWS + row];
        float m = (i % 5 == 4) ? mF : mH;
        tv[nl] = v; ti[nl] = i; ++nl;
        mloc = fminf(mloc, v + m);
    }
    for (int i = tid; i < DIM; i += 128) zs[i] = z[(size_t)row * DIM + i];
    if (tid == 0) cnt = 0;
    smin[tid] = mloc;
    __syncthreads();
    for (int s = 64; s > 0; s >>= 1) {
        if (tid < s) smin[tid] = fminf(smin[tid], smin[tid + s]);
        __syncthreads();
    }
    const float tau = smin[0];
    for (int u = 0; u < nl; ++u) {
        float m = (ti[u] % 5 == 4) ? mF : mH;
        if (tv[u] - m <= tau) { int k = atomicAdd(&cnt, 1); if (k < 64) list[k] = ti[u]; }
    }
    __syncthreads();
    const int nc = min(cnt, 64);

    float bv = CUDART_INF_F;
    int   bi = 0x7fffffff;
    for (int li = 0; li < nc; ++li) {
        const int t32 = list[li];
        const int item = t32 / 5, sub = t32 % 5;
        const int cb = item * 160 + sub * 32;
        for (int idx = tid; idx < 32 * DIM; idx += 128) {
            int r = idx / DIM, col = idx - r * DIM;
            int code = cb + r;
            stage[r * 145 + col] = (code < KCODES) ? emb[(size_t)code * DIM + col] : 0.f;
        }
        __syncthreads();
        if (tid < 32) {
            int code = cb + tid;
            if (code < KCODES) {
                float acc = 0.f;
                const float* es = &stage[tid * 145];
                #pragma unroll 8
                for (int d = 0; d < DIM; ++d)
                    acc = __fmaf_rn(zs[d], es[d], acc);
                float t1 = __fadd_rn(zn, g_en[code]);
                float dd = __fmaf_rn(acc, -2.f, t1);
                if (dd < bv || (dd == bv && code < bi)) { bv = dd; bi = code; }
            }
        }
        __syncthreads();
    }

    rbv[tid] = bv; rbi[tid] = bi;
    __syncthreads();
    for (int s = 64; s > 0; s >>= 1) {
        if (tid < s) {
            float v2 = rbv[tid + s]; int b2 = rbi[tid + s];
            if (v2 < rbv[tid] || (v2 == rbv[tid] && b2 < rbi[tid])) {
                rbv[tid] = v2; rbi[tid] = b2;
            }
        }
        __syncthreads();
    }
    const int wbi = rbi[0];
    if (tid == 0) out[ZQ_ELEMS + row] = (float)wbi;

    double ls = 0.0;
    for (int i = tid; i < DIM; i += 128) {
        float e = emb[(size_t)wbi * DIM + i];
        out[(size_t)row * DIM + i] = e;
        float dx = e - zs[i];
        ls += (double)dx * dx;
    }
    dred[tid] = ls;
    __syncthreads();
    for (int s = 64; s > 0; s >>= 1) {
        if (tid < s) dred[tid] += dred[tid + s];
        __syncthreads();
    }
    if (tid == 0) g_rowloss[row] = dred[0];
}

__global__ void loss_kernel(float* __restrict__ out)
{
    __shared__ double dred[1024];
    int tid = threadIdx.x;
    double s = 0.0;
    for (int i = tid; i < N_ROWS; i += 1024) s += g_rowloss[i];
    dred[tid] = s;
    __syncthreads();
    for (int st = 512; st > 0; st >>= 1) {
        if (tid < st) dred[tid] += dred[tid + st];
        __syncthreads();
    }
    if (tid == 0) out[ZQ_ELEMS + N_ROWS] = (float)(dred[0] / (double)ZQ_ELEMS);
}

// ---------------------------------------------------------------------------
extern "C" void kernel_launch(void* const* d_in, const int* in_sizes, int n_in,
                              void* d_out, int out_size)
{
    const float* z = nullptr;
    const float* emb = nullptr;
    for (int i = 0; i < n_in; ++i) {
        if (in_sizes[i] == N_ROWS * DIM)      z = (const float*)d_in[i];
        else if (in_sizes[i] == KCODES * DIM) emb = (const float*)d_in[i];
    }
    float* out = (float*)d_out;
    (void)out_size;

    cudaFuncSetAttribute(gemm_kernel,
                         cudaFuncAttributeMaxDynamicSharedMemorySize, SMEM_GM);

    prep_kernel<<<(KPADC + 255) / 256, 256>>>(z, emb);
    gemm_kernel<<<NBLK, 256, SMEM_GM>>>();
    rescore_kernel<<<N_ROWS, 128>>>(z, emb, out);
    loss_kernel<<<1, 1024>>>(out);
}

// round 15
// speedup vs baseline: 1.9076x; 1.9076x over previous
#include <cuda_runtime.h>
#include <cuda_fp16.h>
#include <math_constants.h>
#include <stdint.h>

#define N_ROWS 4096
#define DIM    144
#define KCODES 50257
#define KPADC  50304                 // 393 * 128
#define KP     152                   // padded f16 row width (304 bytes)
#define NT128  393
#define NT32   (NT128 * 4)           // 1572
#define NRB    16
#define ITEMS  (NRB * NT128)         // 6288
#define NBLK   148
#define ZQ_ELEMS (N_ROWS * DIM)
#define RRB    32                    // rows per rescore block
#define RBLK   (N_ROWS / RRB)        // 128
#define CAP    4096

#define ESCALE   16384.0f            // 2^14, exact
#define DCOEF    (-1.220703125e-4f)  // -2 * 2^-14, exact

#define OFF_B    77824
#define BBUF     38912
#define OFF_ENS  155648
#define SMEM_GM  156672

// ---- scratch ----
__device__ float   g_zn[N_ROWS];
__device__ float   g_en[KPADC];
__device__ __half  g_zh[(size_t)N_ROWS * KP];
__device__ __half  g_eh[(size_t)KPADC * KP];
__device__ float   g_tmin[(size_t)NT32 * N_ROWS];
__device__ double  g_blockloss[RBLK];
__device__ int     g_rs_cnt;

__device__ __forceinline__ uint32_t smem_u32(const void* p) {
    uint32_t a;
    asm("{ .reg .u64 t; cvta.to.shared.u64 t, %1; cvt.u32.u64 %0, t; }" : "=r"(a) : "l"(p));
    return a;
}
#define CP_ASYNC16(dst, src) \
    asm volatile("cp.async.cg.shared.global [%0], [%1], 16;" :: "r"(dst), "l"(src) : "memory")
#define CP_COMMIT() asm volatile("cp.async.commit_group;" ::: "memory")
#define CP_WAIT1()  asm volatile("cp.async.wait_group 1;" ::: "memory")
#define LDM4(r, addr) \
    asm volatile("ldmatrix.sync.aligned.m8n8.x4.shared.b16 {%0,%1,%2,%3}, [%4];" \
        : "=r"((r)[0]), "=r"((r)[1]), "=r"((r)[2]), "=r"((r)[3]) : "r"(addr))

__device__ __forceinline__ void mma_f16(uint32_t* c, const uint32_t* a, const uint32_t* b)
{
    asm volatile(
        "mma.sync.aligned.m16n8k16.row.col.f16.f16.f16.f16 "
        "{%0,%1}, {%2,%3,%4,%5}, {%6,%7}, {%0,%1};\n"
        : "+r"(c[0]), "+r"(c[1])
        : "r"(a[0]), "r"(a[1]), "r"(a[2]), "r"(a[3]), "r"(b[0]), "r"(b[1]));
}

// ---------------------------------------------------------------------------
// Kernel 1: exact norms (bit-matching NEON order) + fp16 copies (R12-proven).
// ---------------------------------------------------------------------------
__global__ void prep_kernel(const float* __restrict__ z,
                            const float* __restrict__ emb)
{
    int gid = blockIdx.x * blockDim.x + threadIdx.x;
    __half2 zero2 = __floats2half2_rn(0.f, 0.f);
    if (gid == 0) g_rs_cnt = 0;

    if (gid < N_ROWS) {
        const float4* p = reinterpret_cast<const float4*>(z + (size_t)gid * DIM);
        __half2* dst = reinterpret_cast<__half2*>(g_zh + (size_t)gid * KP);
        float p0 = 0.f, p1 = 0.f, p2 = 0.f, p3 = 0.f;
        #pragma unroll
        for (int i = 0; i < DIM / 4; ++i) {
            float4 v = p[i];
            p0 = __fmaf_rn(v.x, v.x, p0);
            p1 = __fmaf_rn(v.y, v.y, p1);
            p2 = __fmaf_rn(v.z, v.z, p2);
            p3 = __fmaf_rn(v.w, v.w, p3);
            dst[i * 2 + 0] = __floats2half2_rn(v.x, v.y);
            dst[i * 2 + 1] = __floats2half2_rn(v.z, v.w);
        }
        #pragma unroll
        for (int i = 72; i < KP / 2; ++i) dst[i] = zero2;
        g_zn[gid] = __fadd_rn(__fadd_rn(p0, p1), __fadd_rn(p2, p3));
    }

    if (gid < KPADC) {
        __half2* dst = reinterpret_cast<__half2*>(g_eh + (size_t)gid * KP);
        if (gid < KCODES) {
            const float4* p = reinterpret_cast<const float4*>(emb + (size_t)gid * DIM);
            float p0 = 0.f, p1 = 0.f, p2 = 0.f, p3 = 0.f;
            #pragma unroll
            for (int i = 0; i < DIM / 4; ++i) {
                float4 v = p[i];
                p0 = __fmaf_rn(v.x, v.x, p0);
                p1 = __fmaf_rn(v.y, v.y, p1);
                p2 = __fmaf_rn(v.z, v.z, p2);
                p3 = __fmaf_rn(v.w, v.w, p3);
                dst[i * 2 + 0] = __floats2half2_rn(v.x * ESCALE, v.y * ESCALE);
                dst[i * 2 + 1] = __floats2half2_rn(v.z * ESCALE, v.w * ESCALE);
            }
            #pragma unroll
            for (int i = 72; i < KP / 2; ++i) dst[i] = zero2;
            g_en[gid] = __fadd_rn(__fadd_rn(p0, p1), __fadd_rn(p2, p3));
        } else {
            for (int i = 0; i < KP / 2; ++i) dst[i] = zero2;
            g_en[gid] = CUDART_INF_F;
        }
    }
}

// ---------------------------------------------------------------------------
// Kernel 2: persistent f16 mma.sync GEMM (identical to the 490us R12 kernel),
// epilogue now emits 32-wide tile mins (4 per 128-code item).
// ---------------------------------------------------------------------------
__device__ __forceinline__ void prefetch_b(int ct, int buf, int tid,
                                           uint32_t bs_addr, uint32_t ens_addr)
{
    const char* src = reinterpret_cast<const char*>(g_eh) + (size_t)ct * 128 * 304;
    uint32_t dst = bs_addr + buf * BBUF;
    #pragma unroll 5
    for (int i = tid; i < 2432; i += 256)
        CP_ASYNC16(dst + i * 16, src + (size_t)i * 16);
    if (tid < 32)
        CP_ASYNC16(ens_addr + buf * 512 + tid * 16,
                   reinterpret_cast<const char*>(g_en + ct * 128) + tid * 16);
    CP_COMMIT();
}

__global__ void __launch_bounds__(256, 1) gemm_kernel()
{
    extern __shared__ char sm[];
    char* As = sm;

    const int tid  = threadIdx.x;
    const int lane = tid & 31;
    const int wid  = tid >> 5;
    const int wm   = wid >> 1;
    const int wn   = wid & 1;
    const int g    = lane >> 2;
    const int q    = lane & 3;

    const uint32_t sbase    = smem_u32(sm);
    const uint32_t bs_addr  = sbase + OFF_B;
    const uint32_t ens_addr = sbase + OFF_ENS;

    const int aRow = (lane & 7) + ((lane >> 3) & 1) * 8;
    const int aK16 = (lane >> 4);
    const int bRow = (lane & 7) + (lane >> 4) * 8;
    const int bK16 = (lane >> 3) & 1;

    const uint32_t aBase  = sbase   + (uint32_t)(wm * 64 + aRow) * 304 + aK16 * 16;
    const uint32_t bBase0 = bs_addr + (uint32_t)(wn * 64 + bRow) * 304 + bK16 * 16;

    const int per = ITEMS / NBLK;
    const int rem = ITEMS - per * NBLK;
    int it = blockIdx.x * per + min((int)blockIdx.x, rem);
    const int iend = it + per + (blockIdx.x < rem ? 1 : 0);

    prefetch_b(it % NT128, it & 1, tid, bs_addr, ens_addr);

    int cur_rb = -1;
    float znr[4][2];

    for (; it < iend; ++it) {
        const int rb = it / NT128;
        const int ct = it - rb * NT128;

        if (it + 1 < iend) prefetch_b((it + 1) % NT128, (it + 1) & 1, tid, bs_addr, ens_addr);
        else               CP_COMMIT();

        if (rb != cur_rb) {
            cur_rb = rb;
            const uint4* src = reinterpret_cast<const uint4*>(g_zh + (size_t)rb * 256 * KP);
            uint4* dst = reinterpret_cast<uint4*>(As);
            #pragma unroll 4
            for (int i = tid; i < 4864; i += 256) dst[i] = src[i];
            #pragma unroll
            for (int mi = 0; mi < 4; ++mi)
                #pragma unroll
                for (int rh = 0; rh < 2; ++rh)
                    znr[mi][rh] = g_zn[rb * 256 + wm * 64 + mi * 16 + rh * 8 + g];
        }

        CP_WAIT1();
        __syncthreads();

        const uint32_t bB = bBase0 + (it & 1) * BBUF;
        const float* eb = reinterpret_cast<const float*>(sm + OFF_ENS) + (it & 1) * 128 + wn * 64;

        uint32_t c[4][8][2];
        #pragma unroll
        for (int mi = 0; mi < 4; ++mi)
            #pragma unroll
            for (int ni = 0; ni < 8; ++ni) { c[mi][ni][0] = 0u; c[mi][ni][1] = 0u; }

        #pragma unroll
        for (int ks = 0; ks < 9; ++ks) {
            uint32_t b[4][4];
            #pragma unroll
            for (int p = 0; p < 4; ++p)
                LDM4(b[p], bB + p * (16 * 304) + ks * 32);
            #pragma unroll
            for (int mi = 0; mi < 4; ++mi) {
                uint32_t a[4];
                LDM4(a, aBase + mi * (16 * 304) + ks * 32);
                #pragma unroll
                for (int p = 0; p < 4; ++p) {
                    mma_f16(c[mi][2 * p + 0], a, &b[p][0]);
                    mma_f16(c[mi][2 * p + 1], a, &b[p][2]);
                }
            }
        }

        // Epilogue: per-row min over two 32-code sub-tiles of this warp half.
        float vmin[2][4][2];
        #pragma unroll
        for (int h = 0; h < 2; ++h)
            #pragma unroll
            for (int mi = 0; mi < 4; ++mi)
                { vmin[h][mi][0] = CUDART_INF_F; vmin[h][mi][1] = CUDART_INF_F; }

        #pragma unroll
        for (int ni = 0; ni < 8; ++ni) {
            const int noff = (ni >> 1) * 16 + (ni & 1) * 8;   // ni 0..3 -> cols 0..31
            const int h = ni >> 2;
            float2 e = *reinterpret_cast<const float2*>(eb + noff + q * 2);
            #pragma unroll
            for (int mi = 0; mi < 4; ++mi) {
                float2 lo = __half22float2(*reinterpret_cast<const __half2*>(&c[mi][ni][0]));
                float2 hi = __half22float2(*reinterpret_cast<const __half2*>(&c[mi][ni][1]));
                vmin[h][mi][0] = fminf(vmin[h][mi][0], __fmaf_rn(lo.x, DCOEF, znr[mi][0] + e.x));
                vmin[h][mi][0] = fminf(vmin[h][mi][0], __fmaf_rn(lo.y, DCOEF, znr[mi][0] + e.y));
                vmin[h][mi][1] = fminf(vmin[h][mi][1], __fmaf_rn(hi.x, DCOEF, znr[mi][1] + e.x));
                vmin[h][mi][1] = fminf(vmin[h][mi][1], __fmaf_rn(hi.y, DCOEF, znr[mi][1] + e.y));
            }
        }
        #pragma unroll
        for (int h = 0; h < 2; ++h)
            #pragma unroll
            for (int mi = 0; mi < 4; ++mi)
                #pragma unroll
                for (int rh = 0; rh < 2; ++rh) {
                    float v = vmin[h][mi][rh];
                    v = fminf(v, __shfl_xor_sync(0xffffffffu, v, 1));
                    v = fminf(v, __shfl_xor_sync(0xffffffffu, v, 2));
                    vmin[h][mi][rh] = v;
                }
        if (q == 0) {
            #pragma unroll
            for (int h = 0; h < 2; ++h) {
                const size_t base = (size_t)(4 * ct + wn * 2 + h) * N_ROWS
                                  + rb * 256 + wm * 64;
                #pragma unroll
                for (int mi = 0; mi < 4; ++mi)
                    #pragma unroll
                    for (int rh = 0; rh < 2; ++rh)
                        g_tmin[base + mi * 16 + rh * 8 + g] = vmin[h][mi][rh];
            }
        }
        __syncthreads();
    }
}

// ---------------------------------------------------------------------------
// Kernel 3: rescore, 128 blocks x 32 rows. Coalesced tmin, worklist,
// order-independent atomicMin argmin (exact lexicographic), fused loss.
// ---------------------------------------------------------------------------
__device__ __forceinline__ void exact_dot_update(
    const float* __restrict__ emb, const float* zr, float zn, int code,
    unsigned long long* bslot)
{
    const float4* ep = reinterpret_cast<const float4*>(emb + (size_t)code * DIM);
    float acc = 0.f;
    #pragma unroll 9
    for (int c4 = 0; c4 < 36; ++c4) {
        float4 e4 = ep[c4];
        acc = __fmaf_rn(zr[4 * c4 + 0], e4.x, acc);
        acc = __fmaf_rn(zr[4 * c4 + 1], e4.y, acc);
        acc = __fmaf_rn(zr[4 * c4 + 2], e4.z, acc);
        acc = __fmaf_rn(zr[4 * c4 + 3], e4.w, acc);
    }
    float t1v = __fadd_rn(zn, g_en[code]);
    float dd  = __fmaf_rn(acc, -2.f, t1v);
    unsigned long long key =
        ((unsigned long long)__float_as_uint(dd) << 32) | (unsigned)code;
    atomicMin(bslot, key);
}

__global__ void __launch_bounds__(128) rescore_kernel(const float* __restrict__ z,
                                                      const float* __restrict__ emb,
                                                      float* __restrict__ out)
{
    __shared__ float  zs[RRB * DIM];
    __shared__ float  warpmin[4][RRB];
    __shared__ float  tau[RRB];
    __shared__ float  znsh[RRB];
    __shared__ int    list[CAP];
    __shared__ int    cnt, ovf;
    __shared__ unsigned long long best[RRB];
    __shared__ double dsum[128];
    __shared__ int    amLast;

    const int tid  = threadIdx.x;
    const int lane = tid & 31;
    const int w    = tid >> 5;
    const int rowbase = blockIdx.x * RRB;

    for (int i = tid; i < RRB * DIM; i += 128)
        zs[i] = z[(size_t)rowbase * DIM + i];
    if (tid < RRB) { znsh[tid] = g_zn[rowbase + tid]; best[tid] = ~0ULL; }
    if (tid == 0) { cnt = 0; ovf = 0; }
    __syncthreads();

    // phase A: per-row min over all tiles (coalesced: lane = row)
    const int TPW = NT32 / 4;   // 393
    {
        float m0 = CUDART_INF_F, m1 = CUDART_INF_F;
        const float* base = g_tmin + rowbase + lane;
        const int t0 = w * TPW;
        #pragma unroll 4
        for (int t = t0; t + 1 < t0 + TPW; t += 2) {
            m0 = fminf(m0, base[(size_t)t * N_ROWS]);
            m1 = fminf(m1, base[(size_t)(t + 1) * N_ROWS]);
        }
        m0 = fminf(m0, base[(size_t)(t0 + TPW - 1) * N_ROWS]);  // TPW odd
        warpmin[w][lane] = fminf(m0, m1);
    }
    __syncthreads();
    if (tid < RRB) {
        float m = fminf(fminf(warpmin[0][tid], warpmin[1][tid]),
                        fminf(warpmin[2][tid], warpmin[3][tid]));
        tau[tid] = m + 4e-5f + 4e-6f * sqrtf(znsh[tid]);   // R12-proven margin
    }
    __syncthreads();

    // phase B: worklist of (tile, row) within margin
    {
        const float* base = g_tmin + rowbase + lane;
        const float mytau = tau[lane];
        const int t0 = w * TPW;
        for (int t = t0; t < t0 + TPW; ++t) {
            float v = base[(size_t)t * N_ROWS];
            if (v <= mytau) {
                int k = atomicAdd(&cnt, 1);
                if (k < CAP) list[k] = (t << 5) | lane;
                else ovf = 1;
            }
        }
    }
    __syncthreads();
    const int nc = min(cnt, CAP);

    // phase C: exact dots, one (row,code) per virtual task
    for (int v = tid; v < nc * 32; v += 128) {
        const int e    = list[v >> 5];
        const int off  = v & 31;
        const int rloc = e & 31;
        const int t32  = e >> 5;
        const int code = (t32 >> 2) * 128 + (t32 & 3) * 32 + off;
        if (code < KCODES)
            exact_dot_update(emb, zs + rloc * DIM, znsh[rloc], code, &best[rloc]);
    }
    if (ovf) {   // sound fallback (never expected): inline scan, idempotent
        for (int vv = tid; vv < NT32 * RRB; vv += 128) {
            const int t32 = vv >> 5, rloc = vv & 31;
            float val = g_tmin[(size_t)t32 * N_ROWS + rowbase + rloc];
            if (val <= tau[rloc]) {
                const int cb = (t32 >> 2) * 128 + (t32 & 3) * 32;
                for (int off = 0; off < 32; ++off)
                    if (cb + off < KCODES)
                        exact_dot_update(emb, zs + rloc * DIM, znsh[rloc],
                                         cb + off, &best[rloc]);
            }
        }
    }
    __syncthreads();

    // phase D: indices, z_q, loss
    if (tid < RRB)
        out[ZQ_ELEMS + rowbase + tid] = (float)(int)(best[tid] & 0xffffffffu);
    {
        const int rloc = tid >> 2, qd = tid & 3;
        const int code = (int)(best[rloc] & 0xffffffffu);
        const float* ep = emb + (size_t)code * DIM;
        double ls = 0.0;
        #pragma unroll 9
        for (int d = qd * 36; d < qd * 36 + 36; ++d) {
            float e = ep[d];
            out[(size_t)(rowbase + rloc) * DIM + d] = e;
            float dx = e - zs[rloc * DIM + d];
            ls += (double)dx * dx;
        }
        dsum[tid] = ls;
    }
    __syncthreads();
    for (int s = 64; s > 0; s >>= 1) {
        if (tid < s) dsum[tid] += dsum[tid + s];
        __syncthreads();
    }
    if (tid == 0) g_blockloss[blockIdx.x] = dsum[0];
    __threadfence();
    if (tid == 0) amLast = (atomicAdd(&g_rs_cnt, 1) == RBLK - 1);
    __syncthreads();
    if (amLast) {
        dsum[tid] = g_blockloss[tid];   // RBLK == 128
        __syncthreads();
        for (int s = 64; s > 0; s >>= 1) {
            if (tid < s) dsum[tid] += dsum[tid + s];
            __syncthreads();
        }
        if (tid == 0) {
            out[ZQ_ELEMS + N_ROWS] = (float)(dsum[0] / (double)ZQ_ELEMS);
            g_rs_cnt = 0;
        }
    }
}

// ---------------------------------------------------------------------------
extern "C" void kernel_launch(void* const* d_in, const int* in_sizes, int n_in,
                              void* d_out, int out_size)
{
    const float* z = nullptr;
    const float* emb = nullptr;
    for (int i = 0; i < n_in; ++i) {
        if (in_sizes[i] == N_ROWS * DIM)      z = (const float*)d_in[i];
        else if (in_sizes[i] == KCODES * DIM) emb = (const float*)d_in[i];
    }
    float* out = (float*)d_out;
    (void)out_size;

    cudaFuncSetAttribute(gemm_kernel,
                         cudaFuncAttributeMaxDynamicSharedMemorySize, SMEM_GM);

    prep_kernel<<<(KPADC + 255) / 256, 256>>>(z, emb);
    gemm_kernel<<<NBLK, 256, SMEM_GM>>>();
    rescore_kernel<<<RBLK, 128>>>(z, emb, out);
}

// round 16
// speedup vs baseline: 2.0870x; 1.0941x over previous
#include <cuda_runtime.h>
#include <cuda_fp16.h>
#include <math_constants.h>
#include <stdint.h>

#define N_ROWS 4096
#define DIM    144
#define KCODES 50257
#define KPADC  50304                 // 393 * 128 = 786 * 64
#define KP     152                   // padded f16 row width (304 bytes)
#define NT128  393
#define NT32   (NT128 * 4)           // 1572
#define NRB    16
#define ITEMS  (NRB * NT128)         // 6288
#define NBLK   148
#define ZQ_ELEMS (N_ROWS * DIM)
#define RRB    32                    // rows per rescore block
#define RBLK   (N_ROWS / RRB)        // 128
#define CAP    4096

#define ESCALE   16384.0f            // 2^14, exact
#define DCOEF    (-1.220703125e-4f)  // -2 * 2^-14, exact

#define OFF_B    77824
#define BBUF     38912
#define OFF_ENS  155648
#define SMEM_GM  156672

// prep tiling
#define PROWS    64
#define PSTRIDE  148                 // smem floats per row: conflict-free
#define EBLOCKS  (KPADC / PROWS)     // 786
#define PBLOCKS  (EBLOCKS + N_ROWS / PROWS)  // 850

// ---- scratch ----
__device__ float   g_zn[N_ROWS];
__device__ float   g_en[KPADC];
__device__ __half  g_zh[(size_t)N_ROWS * KP];
__device__ __half  g_eh[(size_t)KPADC * KP];
__device__ float   g_tmin[(size_t)NT32 * N_ROWS];
__device__ double  g_blockloss[RBLK];
__device__ int     g_rs_cnt;

__device__ __forceinline__ uint32_t smem_u32(const void* p) {
    uint32_t a;
    asm("{ .reg .u64 t; cvta.to.shared.u64 t, %1; cvt.u32.u64 %0, t; }" : "=r"(a) : "l"(p));
    return a;
}
#define CP_ASYNC16(dst, src) \
    asm volatile("cp.async.cg.shared.global [%0], [%1], 16;" :: "r"(dst), "l"(src) : "memory")
#define CP_COMMIT() asm volatile("cp.async.commit_group;" ::: "memory")
#define CP_WAIT1()  asm volatile("cp.async.wait_group 1;" ::: "memory")
#define LDM4(r, addr) \
    asm volatile("ldmatrix.sync.aligned.m8n8.x4.shared.b16 {%0,%1,%2,%3}, [%4];" \
        : "=r"((r)[0]), "=r"((r)[1]), "=r"((r)[2]), "=r"((r)[3]) : "r"(addr))

__device__ __forceinline__ void mma_f16(uint32_t* c, const uint32_t* a, const uint32_t* b)
{
    asm volatile(
        "mma.sync.aligned.m16n8k16.row.col.f16.f16.f16.f16 "
        "{%0,%1}, {%2,%3,%4,%5}, {%6,%7}, {%0,%1};\n"
        : "+r"(c[0]), "+r"(c[1])
        : "r"(a[0]), "r"(a[1]), "r"(a[2]), "r"(a[3]), "r"(b[0]), "r"(b[1]));
}

// ---------------------------------------------------------------------------
// Kernel 1: prep. 64 rows/block staged via smem (coalesced). Norms use
// 4 threads/row: identical per-lane FMA chains + bitwise-commutative fadd
// combine => bit-identical to the proven NEON order. fp16 copies coalesced.
// Blocks [0,786): emb (incl. padding), [786,850): z.
// ---------------------------------------------------------------------------
__global__ void __launch_bounds__(256) prep_kernel(const float* __restrict__ z,
                                                   const float* __restrict__ emb)
{
    __shared__ float smf[PROWS * PSTRIDE];

    const int tid = threadIdx.x;
    const int blk = blockIdx.x;
    const bool isZ = blk >= EBLOCKS;
    const int rowbase = (isZ ? blk - EBLOCKS : blk) * PROWS;
    const int avail = isZ ? PROWS : min(PROWS, KCODES - rowbase);
    const float* src = (isZ ? z : emb) + (size_t)rowbase * DIM;
    const float sc = isZ ? 1.0f : ESCALE;

    if (blk == 0 && tid == 0) g_rs_cnt = 0;

    // coalesced load of 64 rows (rows beyond avail -> 0)
    for (int i = tid; i < PROWS * (DIM / 4); i += 256) {
        const int r = i / (DIM / 4);
        const int c4 = i - r * (DIM / 4);
        float4 v = make_float4(0.f, 0.f, 0.f, 0.f);
        if (r < avail)
            v = *reinterpret_cast<const float4*>(src + (size_t)r * DIM + c4 * 4);
        *reinterpret_cast<float4*>(&smf[r * PSTRIDE + c4 * 4]) = v;
    }
    __syncthreads();

    // norms: 4 threads per row, chains p_t identical to serial NEON order
    {
        const int rloc = tid >> 2, t = tid & 3;
        const float* rowp = smf + rloc * PSTRIDE + t;
        float p = 0.f;
        #pragma unroll
        for (int i = 0; i < DIM / 4; ++i) {
            float v = rowp[4 * i];
            p = __fmaf_rn(v, v, p);
        }
        float s  = __fadd_rn(p, __shfl_xor_sync(0xffffffffu, p, 1));
        float nm = __fadd_rn(s, __shfl_xor_sync(0xffffffffu, s, 2));
        if (t == 0) {
            const int row = rowbase + rloc;
            if (isZ)               g_zn[row] = nm;
            else                   g_en[row] = (rloc < avail) ? nm : CUDART_INF_F;
        }
    }

    // fp16 conversion: coalesced half2 stores, pad cols [144,152) = 0
    {
        __half2* dst = (isZ ? reinterpret_cast<__half2*>(g_zh)
                            : reinterpret_cast<__half2*>(g_eh))
                       + (size_t)rowbase * (KP / 2);
        const __half2 zero2 = __floats2half2_rn(0.f, 0.f);
        for (int i = tid; i < PROWS * (KP / 2); i += 256) {
            const int r = i / (KP / 2);
            const int c2 = i - r * (KP / 2);
            __half2 h = zero2;
            if (c2 < DIM / 2)
                h = __floats2half2_rn(smf[r * PSTRIDE + 2 * c2] * sc,
                                      smf[r * PSTRIDE + 2 * c2 + 1] * sc);
            dst[(size_t)r * (KP / 2) + c2] = h;
        }
    }
}

// ---------------------------------------------------------------------------
// Kernel 2: persistent f16 mma.sync GEMM (byte-identical to the 377us R15
// kernel): tile 256x128, ldmatrix + cp.async, 32-wide tile mins.
// ---------------------------------------------------------------------------
__device__ __forceinline__ void prefetch_b(int ct, int buf, int tid,
                                           uint32_t bs_addr, uint32_t ens_addr)
{
    const char* src = reinterpret_cast<const char*>(g_eh) + (size_t)ct * 128 * 304;
    uint32_t dst = bs_addr + buf * BBUF;
    #pragma unroll 5
    for (int i = tid; i < 2432; i += 256)
        CP_ASYNC16(dst + i * 16, src + (size_t)i * 16);
    if (tid < 32)
        CP_ASYNC16(ens_addr + buf * 512 + tid * 16,
                   reinterpret_cast<const char*>(g_en + ct * 128) + tid * 16);
    CP_COMMIT();
}

__global__ void __launch_bounds__(256, 1) gemm_kernel()
{
    extern __shared__ char sm[];
    char* As = sm;

    const int tid  = threadIdx.x;
    const int lane = tid & 31;
    const int wid  = tid >> 5;
    const int wm   = wid >> 1;
    const int wn   = wid & 1;
    const int g    = lane >> 2;
    const int q    = lane & 3;

    const uint32_t sbase    = smem_u32(sm);
    const uint32_t bs_addr  = sbase + OFF_B;
    const uint32_t ens_addr = sbase + OFF_ENS;

    const int aRow = (lane & 7) + ((lane >> 3) & 1) * 8;
    const int aK16 = (lane >> 4);
    const int bRow = (lane & 7) + (lane >> 4) * 8;
    const int bK16 = (lane >> 3) & 1;

    const uint32_t aBase  = sbase   + (uint32_t)(wm * 64 + aRow) * 304 + aK16 * 16;
    const uint32_t bBase0 = bs_addr + (uint32_t)(wn * 64 + bRow) * 304 + bK16 * 16;

    const int per = ITEMS / NBLK;
    const int rem = ITEMS - per * NBLK;
    int it = blockIdx.x * per + min((int)blockIdx.x, rem);
    const int iend = it + per + (blockIdx.x < rem ? 1 : 0);

    prefetch_b(it % NT128, it & 1, tid, bs_addr, ens_addr);

    int cur_rb = -1;
    float znr[4][2];

    for (; it < iend; ++it) {
        const int rb = it / NT128;
        const int ct = it - rb * NT128;

        if (it + 1 < iend) prefetch_b((it + 1) % NT128, (it + 1) & 1, tid, bs_addr, ens_addr);
        else               CP_COMMIT();

        if (rb != cur_rb) {
            cur_rb = rb;
            const uint4* src = reinterpret_cast<const uint4*>(g_zh + (size_t)rb * 256 * KP);
            uint4* dst = reinterpret_cast<uint4*>(As);
            #pragma unroll 4
            for (int i = tid; i < 4864; i += 256) dst[i] = src[i];
            #pragma unroll
            for (int mi = 0; mi < 4; ++mi)
                #pragma unroll
                for (int rh = 0; rh < 2; ++rh)
                    znr[mi][rh] = g_zn[rb * 256 + wm * 64 + mi * 16 + rh * 8 + g];
        }

        CP_WAIT1();
        __syncthreads();

        const uint32_t bB = bBase0 + (it & 1) * BBUF;
        const float* eb = reinterpret_cast<const float*>(sm + OFF_ENS) + (it & 1) * 128 + wn * 64;

        uint32_t c[4][8][2];
        #pragma unroll
        for (int mi = 0; mi < 4; ++mi)
            #pragma unroll
            for (int ni = 0; ni < 8; ++ni) { c[mi][ni][0] = 0u; c[mi][ni][1] = 0u; }

        #pragma unroll
        for (int ks = 0; ks < 9; ++ks) {
            uint32_t b[4][4];
            #pragma unroll
            for (int p = 0; p < 4; ++p)
                LDM4(b[p], bB + p * (16 * 304) + ks * 32);
            #pragma unroll
            for (int mi = 0; mi < 4; ++mi) {
                uint32_t a[4];
                LDM4(a, aBase + mi * (16 * 304) + ks * 32);
                #pragma unroll
                for (int p = 0; p < 4; ++p) {
                    mma_f16(c[mi][2 * p + 0], a, &b[p][0]);
                    mma_f16(c[mi][2 * p + 1], a, &b[p][2]);
                }
            }
        }

        float vmin[2][4][2];
        #pragma unroll
        for (int h = 0; h < 2; ++h)
            #pragma unroll
            for (int mi = 0; mi < 4; ++mi)
                { vmin[h][mi][0] = CUDART_INF_F; vmin[h][mi][1] = CUDART_INF_F; }

        #pragma unroll
        for (int ni = 0; ni < 8; ++ni) {
            const int noff = (ni >> 1) * 16 + (ni & 1) * 8;
            const int h = ni >> 2;
            float2 e = *reinterpret_cast<const float2*>(eb + noff + q * 2);
            #pragma unroll
            for (int mi = 0; mi < 4; ++mi) {
                float2 lo = __half22float2(*reinterpret_cast<const __half2*>(&c[mi][ni][0]));
                float2 hi = __half22float2(*reinterpret_cast<const __half2*>(&c[mi][ni][1]));
                vmin[h][mi][0] = fminf(vmin[h][mi][0], __fmaf_rn(lo.x, DCOEF, znr[mi][0] + e.x));
                vmin[h][mi][0] = fminf(vmin[h][mi][0], __fmaf_rn(lo.y, DCOEF, znr[mi][0] + e.y));
                vmin[h][mi][1] = fminf(vmin[h][mi][1], __fmaf_rn(hi.x, DCOEF, znr[mi][1] + e.x));
                vmin[h][mi][1] = fminf(vmin[h][mi][1], __fmaf_rn(hi.y, DCOEF, znr[mi][1] + e.y));
            }
        }
        #pragma unroll
        for (int h = 0; h < 2; ++h)
            #pragma unroll
            for (int mi = 0; mi < 4; ++mi)
                #pragma unroll
                for (int rh = 0; rh < 2; ++rh) {
                    float v = vmin[h][mi][rh];
                    v = fminf(v, __shfl_xor_sync(0xffffffffu, v, 1));
                    v = fminf(v, __shfl_xor_sync(0xffffffffu, v, 2));
                    vmin[h][mi][rh] = v;
                }
        if (q == 0) {
            #pragma unroll
            for (int h = 0; h < 2; ++h) {
                const size_t base = (size_t)(4 * ct + wn * 2 + h) * N_ROWS
                                  + rb * 256 + wm * 64;
                #pragma unroll
                for (int mi = 0; mi < 4; ++mi)
                    #pragma unroll
                    for (int rh = 0; rh < 2; ++rh)
                        g_tmin[base + mi * 16 + rh * 8 + g] = vmin[h][mi][rh];
            }
        }
        __syncthreads();
    }
}

// ---------------------------------------------------------------------------
// Kernel 3: rescore (byte-identical to the 377us R15 kernel).
// ---------------------------------------------------------------------------
__device__ __forceinline__ void exact_dot_update(
    const float* __restrict__ emb, const float* zr, float zn, int code,
    unsigned long long* bslot)
{
    const float4* ep = reinterpret_cast<const float4*>(emb + (size_t)code * DIM);
    float acc = 0.f;
    #pragma unroll 9
    for (int c4 = 0; c4 < 36; ++c4) {
        float4 e4 = ep[c4];
        acc = __fmaf_rn(zr[4 * c4 + 0], e4.x, acc);
        acc = __fmaf_rn(zr[4 * c4 + 1], e4.y, acc);
        acc = __fmaf_rn(zr[4 * c4 + 2], e4.z, acc);
        acc = __fmaf_rn(zr[4 * c4 + 3], e4.w, acc);
    }
    float t1v = __fadd_rn(zn, g_en[code]);
    float dd  = __fmaf_rn(acc, -2.f, t1v);
    unsigned long long key =
        ((unsigned long long)__float_as_uint(dd) << 32) | (unsigned)code;
    atomicMin(bslot, key);
}

__global__ void __launch_bounds__(128) rescore_kernel(const float* __restrict__ z,
                                                      const float* __restrict__ emb,
                                                      float* __restrict__ out)
{
    __shared__ float  zs[RRB * DIM];
    __shared__ float  warpmin[4][RRB];
    __shared__ float  tau[RRB];
    __shared__ float  znsh[RRB];
    __shared__ int    list[CAP];
    __shared__ int    cnt, ovf;
    __shared__ unsigned long long best[RRB];
    __shared__ double dsum[128];
    __shared__ int    amLast;

    const int tid  = threadIdx.x;
    const int lane = tid & 31;
    const int w    = tid >> 5;
    const int rowbase = blockIdx.x * RRB;

    for (int i = tid; i < RRB * DIM; i += 128)
        zs[i] = z[(size_t)rowbase * DIM + i];
    if (tid < RRB) { znsh[tid] = g_zn[rowbase + tid]; best[tid] = ~0ULL; }
    if (tid == 0) { cnt = 0; ovf = 0; }
    __syncthreads();

    const int TPW = NT32 / 4;   // 393
    {
        float m0 = CUDART_INF_F, m1 = CUDART_INF_F;
        const float* base = g_tmin + rowbase + lane;
        const int t0 = w * TPW;
        #pragma unroll 4
        for (int t = t0; t + 1 < t0 + TPW; t += 2) {
            m0 = fminf(m0, base[(size_t)t * N_ROWS]);
            m1 = fminf(m1, base[(size_t)(t + 1) * N_ROWS]);
        }
        m0 = fminf(m0, base[(size_t)(t0 + TPW - 1) * N_ROWS]);
        warpmin[w][lane] = fminf(m0, m1);
    }
    __syncthreads();
    if (tid < RRB) {
        float m = fminf(fminf(warpmin[0][tid], warpmin[1][tid]),
                        fminf(warpmin[2][tid], warpmin[3][tid]));
        tau[tid] = m + 4e-5f + 4e-6f * sqrtf(znsh[tid]);
    }
    __syncthreads();

    {
        const float* base = g_tmin + rowbase + lane;
        const float mytau = tau[lane];
        const int t0 = w * TPW;
        for (int t = t0; t < t0 + TPW; ++t) {
            float v = base[(size_t)t * N_ROWS];
            if (v <= mytau) {
                int k = atomicAdd(&cnt, 1);
                if (k < CAP) list[k] = (t << 5) | lane;
                else ovf = 1;
            }
        }
    }
    __syncthreads();
    const int nc = min(cnt, CAP);

    for (int v = tid; v < nc * 32; v += 128) {
        const int e    = list[v >> 5];
        const int off  = v & 31;
        const int rloc = e & 31;
        const int t32  = e >> 5;
        const int code = (t32 >> 2) * 128 + (t32 & 3) * 32 + off;
        if (code < KCODES)
            exact_dot_update(emb, zs + rloc * DIM, znsh[rloc], code, &best[rloc]);
    }
    if (ovf) {
        for (int vv = tid; vv < NT32 * RRB; vv += 128) {
            const int t32 = vv >> 5, rloc = vv & 31;
            float val = g_tmin[(size_t)t32 * N_ROWS + rowbase + rloc];
            if (val <= tau[rloc]) {
                const int cb = (t32 >> 2) * 128 + (t32 & 3) * 32;
                for (int off = 0; off < 32; ++off)
                    if (cb + off < KCODES)
                        exact_dot_update(emb, zs + rloc * DIM, znsh[rloc],
                                         cb + off, &best[rloc]);
            }
        }
    }
    __syncthreads();

    if (tid < RRB)
        out[ZQ_ELEMS + rowbase + tid] = (float)(int)(best[tid] & 0xffffffffu);
    {
        const int rloc = tid >> 2, qd = tid & 3;
        const int code = (int)(best[rloc] & 0xffffffffu);
        const float* ep = emb + (size_t)code * DIM;
        double ls = 0.0;
        #pragma unroll 9
        for (int d = qd * 36; d < qd * 36 + 36; ++d) {
            float e = ep[d];
            out[(size_t)(rowbase + rloc) * DIM + d] = e;
            float dx = e - zs[rloc * DIM + d];
            ls += (double)dx * dx;
        }
        dsum[tid] = ls;
    }
    __syncthreads();
    for (int s = 64; s > 0; s >>= 1) {
        if (tid < s) dsum[tid] += dsum[tid + s];
        __syncthreads();
    }
    if (tid == 0) g_blockloss[blockIdx.x] = dsum[0];
    __threadfence();
    if (tid == 0) amLast = (atomicAdd(&g_rs_cnt, 1) == RBLK - 1);
    __syncthreads();
    if (amLast) {
        dsum[tid] = g_blockloss[tid];
        __syncthreads();
        for (int s = 64; s > 0; s >>= 1) {
            if (tid < s) dsum[tid] += dsum[tid + s];
            __syncthreads();
        }
        if (tid == 0) {
            out[ZQ_ELEMS + N_ROWS] = (float)(dsum[0] / (double)ZQ_ELEMS);
            g_rs_cnt = 0;
        }
    }
}

// ---------------------------------------------------------------------------
extern "C" void kernel_launch(void* const* d_in, const int* in_sizes, int n_in,
                              void* d_out, int out_size)
{
    const float* z = nullptr;
    const float* emb = nullptr;
    for (int i = 0; i < n_in; ++i) {
        if (in_sizes[i] == N_ROWS * DIM)      z = (const float*)d_in[i];
        else if (in_sizes[i] == KCODES * DIM) emb = (const float*)d_in[i];
    }
    float* out = (float*)d_out;
    (void)out_size;

    cudaFuncSetAttribute(gemm_kernel,
                         cudaFuncAttributeMaxDynamicSharedMemorySize, SMEM_GM);

    prep_kernel<<<PBLOCKS, 256>>>(z, emb);
    gemm_kernel<<<NBLK, 256, SMEM_GM>>>();
    rescore_kernel<<<RBLK, 128>>>(z, emb, out);
}

// round 17
// speedup vs baseline: 2.1060x; 1.0091x over previous
#include <cuda_runtime.h>
#include <cuda_fp16.h>
#include <math_constants.h>
#include <stdint.h>

#define N_ROWS 4096
#define DIM    144
#define KCODES 50257
#define KPADC  50304                 // 262 * 192 = 786 * 64
#define KP     152                   // padded f16 row width (304 bytes)
#define NT192  262
#define NT32   (NT192 * 6)           // 1572 (unchanged)
#define NRB    16
#define ITEMS  (NRB * NT192)         // 4192
#define NBLK   148
#define ZQ_ELEMS (N_ROWS * DIM)
#define RRB    32
#define RBLK   (N_ROWS / RRB)        // 128
#define CAP    4096

#define ESCALE   16384.0f            // 2^14, exact
#define DCOEF    (-1.220703125e-4f)  // -2 * 2^-14, exact

// smem: A 256x304 | B x2 192x304 | ens x2 192 floats
#define OFF_B    77824
#define BBUF     58368
#define OFF_ENS  194560
#define SMEM_GM  196096

// prep tiling (unchanged from R16)
#define PROWS    64
#define PSTRIDE  148
#define EBLOCKS  (KPADC / PROWS)     // 786
#define PBLOCKS  (EBLOCKS + N_ROWS / PROWS)  // 850

// ---- scratch ----
__device__ float   g_zn[N_ROWS];
__device__ float   g_en[KPADC];
__device__ __half  g_zh[(size_t)N_ROWS * KP];
__device__ __half  g_eh[(size_t)KPADC * KP];
__device__ float   g_tmin[(size_t)NT32 * N_ROWS];
__device__ double  g_blockloss[RBLK];
__device__ int     g_rs_cnt;

__device__ __forceinline__ uint32_t smem_u32(const void* p) {
    uint32_t a;
    asm("{ .reg .u64 t; cvta.to.shared.u64 t, %1; cvt.u32.u64 %0, t; }" : "=r"(a) : "l"(p));
    return a;
}
#define CP_ASYNC16(dst, src) \
    asm volatile("cp.async.cg.shared.global [%0], [%1], 16;" :: "r"(dst), "l"(src) : "memory")
#define CP_COMMIT() asm volatile("cp.async.commit_group;" ::: "memory")
#define CP_WAIT1()  asm volatile("cp.async.wait_group 1;" ::: "memory")
#define LDM4(r, addr) \
    asm volatile("ldmatrix.sync.aligned.m8n8.x4.shared.b16 {%0,%1,%2,%3}, [%4];" \
        : "=r"((r)[0]), "=r"((r)[1]), "=r"((r)[2]), "=r"((r)[3]) : "r"(addr))

__device__ __forceinline__ void mma_f16(uint32_t* c, const uint32_t* a, const uint32_t* b)
{
    asm volatile(
        "mma.sync.aligned.m16n8k16.row.col.f16.f16.f16.f16 "
        "{%0,%1}, {%2,%3,%4,%5}, {%6,%7}, {%0,%1};\n"
        : "+r"(c[0]), "+r"(c[1])
        : "r"(a[0]), "r"(a[1]), "r"(a[2]), "r"(a[3]), "r"(b[0]), "r"(b[1]));
}

// ---------------------------------------------------------------------------
// Kernel 1: prep (byte-identical to the 344us R16 kernel).
// ---------------------------------------------------------------------------
__global__ void __launch_bounds__(256) prep_kernel(const float* __restrict__ z,
                                                   const float* __restrict__ emb)
{
    __shared__ float smf[PROWS * PSTRIDE];

    const int tid = threadIdx.x;
    const int blk = blockIdx.x;
    const bool isZ = blk >= EBLOCKS;
    const int rowbase = (isZ ? blk - EBLOCKS : blk) * PROWS;
    const int avail = isZ ? PROWS : min(PROWS, KCODES - rowbase);
    const float* src = (isZ ? z : emb) + (size_t)rowbase * DIM;
    const float sc = isZ ? 1.0f : ESCALE;

    if (blk == 0 && tid == 0) g_rs_cnt = 0;

    for (int i = tid; i < PROWS * (DIM / 4); i += 256) {
        const int r = i / (DIM / 4);
        const int c4 = i - r * (DIM / 4);
        float4 v = make_float4(0.f, 0.f, 0.f, 0.f);
        if (r < avail)
            v = *reinterpret_cast<const float4*>(src + (size_t)r * DIM + c4 * 4);
        *reinterpret_cast<float4*>(&smf[r * PSTRIDE + c4 * 4]) = v;
    }
    __syncthreads();

    {
        const int rloc = tid >> 2, t = tid & 3;
        const float* rowp = smf + rloc * PSTRIDE + t;
        float p = 0.f;
        #pragma unroll
        for (int i = 0; i < DIM / 4; ++i) {
            float v = rowp[4 * i];
            p = __fmaf_rn(v, v, p);
        }
        float s  = __fadd_rn(p, __shfl_xor_sync(0xffffffffu, p, 1));
        float nm = __fadd_rn(s, __shfl_xor_sync(0xffffffffu, s, 2));
        if (t == 0) {
            const int row = rowbase + rloc;
            if (isZ)               g_zn[row] = nm;
            else                   g_en[row] = (rloc < avail) ? nm : CUDART_INF_F;
        }
    }

    {
        __half2* dst = (isZ ? reinterpret_cast<__half2*>(g_zh)
                            : reinterpret_cast<__half2*>(g_eh))
                       + (size_t)rowbase * (KP / 2);
        const __half2 zero2 = __floats2half2_rn(0.f, 0.f);
        for (int i = tid; i < PROWS * (KP / 2); i += 256) {
            const int r = i / (KP / 2);
            const int c2 = i - r * (KP / 2);
            __half2 h = zero2;
            if (c2 < DIM / 2)
                h = __floats2half2_rn(smf[r * PSTRIDE + 2 * c2] * sc,
                                      smf[r * PSTRIDE + 2 * c2 + 1] * sc);
            dst[(size_t)r * (KP / 2) + c2] = h;
        }
    }
}

// ---------------------------------------------------------------------------
// Kernel 2: persistent f16 mma.sync GEMM, block tile 256 x 192 (was x128).
// Warp tile 64 x 96 (c[4][12][2]); 6 x 32-code sub-mins per item.
// ---------------------------------------------------------------------------
__device__ __forceinline__ void prefetch_b(int ct, int buf, int tid,
                                           uint32_t bs_addr, uint32_t ens_addr)
{
    const char* src = reinterpret_cast<const char*>(g_eh) + (size_t)ct * 192 * 304;
    uint32_t dst = bs_addr + buf * BBUF;
    #pragma unroll 5
    for (int i = tid; i < 3648; i += 256)
        CP_ASYNC16(dst + i * 16, src + (size_t)i * 16);
    if (tid < 48)
        CP_ASYNC16(ens_addr + buf * 768 + tid * 16,
                   reinterpret_cast<const char*>(g_en + ct * 192) + tid * 16);
    CP_COMMIT();
}

__global__ void __launch_bounds__(256, 1) gemm_kernel()
{
    extern __shared__ char sm[];
    char* As = sm;

    const int tid  = threadIdx.x;
    const int lane = tid & 31;
    const int wid  = tid >> 5;
    const int wm   = wid >> 1;       // 0..3 : 64-row slab
    const int wn   = wid & 1;        // 0..1 : 96-code half
    const int g    = lane >> 2;
    const int q    = lane & 3;

    const uint32_t sbase    = smem_u32(sm);
    const uint32_t bs_addr  = sbase + OFF_B;
    const uint32_t ens_addr = sbase + OFF_ENS;

    const int aRow = (lane & 7) + ((lane >> 3) & 1) * 8;
    const int aK16 = (lane >> 4);
    const int bRow = (lane & 7) + (lane >> 4) * 8;
    const int bK16 = (lane >> 3) & 1;

    const uint32_t aBase  = sbase   + (uint32_t)(wm * 64 + aRow) * 304 + aK16 * 16;
    const uint32_t bBase0 = bs_addr + (uint32_t)(wn * 96 + bRow) * 304 + bK16 * 16;

    const int per = ITEMS / NBLK;                 // 28
    const int rem = ITEMS - per * NBLK;           // 48
    int it = blockIdx.x * per + min((int)blockIdx.x, rem);
    const int iend = it + per + (blockIdx.x < rem ? 1 : 0);

    prefetch_b(it % NT192, it & 1, tid, bs_addr, ens_addr);

    int cur_rb = -1;
    float znr[4][2];

    for (; it < iend; ++it) {
        const int rb = it / NT192;
        const int ct = it - rb * NT192;

        if (it + 1 < iend) prefetch_b((it + 1) % NT192, (it + 1) & 1, tid, bs_addr, ens_addr);
        else               CP_COMMIT();

        if (rb != cur_rb) {
            cur_rb = rb;
            const uint4* src = reinterpret_cast<const uint4*>(g_zh + (size_t)rb * 256 * KP);
            uint4* dst = reinterpret_cast<uint4*>(As);
            #pragma unroll 4
            for (int i = tid; i < 4864; i += 256) dst[i] = src[i];
            #pragma unroll
            for (int mi = 0; mi < 4; ++mi)
                #pragma unroll
                for (int rh = 0; rh < 2; ++rh)
                    znr[mi][rh] = g_zn[rb * 256 + wm * 64 + mi * 16 + rh * 8 + g];
        }

        CP_WAIT1();
        __syncthreads();

        const uint32_t bB = bBase0 + (it & 1) * BBUF;
        const float* eb = reinterpret_cast<const float*>(sm + OFF_ENS) + (it & 1) * 192 + wn * 96;

        uint32_t c[4][12][2];
        #pragma unroll
        for (int mi = 0; mi < 4; ++mi)
            #pragma unroll
            for (int ni = 0; ni < 12; ++ni) { c[mi][ni][0] = 0u; c[mi][ni][1] = 0u; }

        #pragma unroll
        for (int ks = 0; ks < 9; ++ks) {
            uint32_t b[6][4];
            #pragma unroll
            for (int p = 0; p < 6; ++p)
                LDM4(b[p], bB + p * (16 * 304) + ks * 32);
            #pragma unroll
            for (int mi = 0; mi < 4; ++mi) {
                uint32_t a[4];
                LDM4(a, aBase + mi * (16 * 304) + ks * 32);
                #pragma unroll
                for (int p = 0; p < 6; ++p) {
                    mma_f16(c[mi][2 * p + 0], a, &b[p][0]);   // n offset p*16
                    mma_f16(c[mi][2 * p + 1], a, &b[p][2]);   // n offset p*16+8
                }
            }
        }

        // Epilogue: per-row min over three 32-code sub-tiles of this warp half.
        float vmin[3][4][2];
        #pragma unroll
        for (int h = 0; h < 3; ++h)
            #pragma unroll
            for (int mi = 0; mi < 4; ++mi)
                { vmin[h][mi][0] = CUDART_INF_F; vmin[h][mi][1] = CUDART_INF_F; }

        #pragma unroll
        for (int ni = 0; ni < 12; ++ni) {
            const int noff = (ni >> 1) * 16 + (ni & 1) * 8;   // 0..88
            const int h = ni >> 2;                            // 32-code sub-tile
            float2 e = *reinterpret_cast<const float2*>(eb + noff + q * 2);
            #pragma unroll
            for (int mi = 0; mi < 4; ++mi) {
                float2 lo = __half22float2(*reinterpret_cast<const __half2*>(&c[mi][ni][0]));
                float2 hi = __half22float2(*reinterpret_cast<const __half2*>(&c[mi][ni][1]));
                vmin[h][mi][0] = fminf(vmin[h][mi][0], __fmaf_rn(lo.x, DCOEF, znr[mi][0] + e.x));
                vmin[h][mi][0] = fminf(vmin[h][mi][0], __fmaf_rn(lo.y, DCOEF, znr[mi][0] + e.y));
                vmin[h][mi][1] = fminf(vmin[h][mi][1], __fmaf_rn(hi.x, DCOEF, znr[mi][1] + e.x));
                vmin[h][mi][1] = fminf(vmin[h][mi][1], __fmaf_rn(hi.y, DCOEF, znr[mi][1] + e.y));
            }
        }
        #pragma unroll
        for (int h = 0; h < 3; ++h)
            #pragma unroll
            for (int mi = 0; mi < 4; ++mi)
                #pragma unroll
                for (int rh = 0; rh < 2; ++rh) {
                    float v = vmin[h][mi][rh];
                    v = fminf(v, __shfl_xor_sync(0xffffffffu, v, 1));
                    v = fminf(v, __shfl_xor_sync(0xffffffffu, v, 2));
                    vmin[h][mi][rh] = v;
                }
        if (q == 0) {
            #pragma unroll
            for (int h = 0; h < 3; ++h) {
                const size_t base = (size_t)(6 * ct + wn * 3 + h) * N_ROWS
                                  + rb * 256 + wm * 64;
                #pragma unroll
                for (int mi = 0; mi < 4; ++mi)
                    #pragma unroll
                    for (int rh = 0; rh < 2; ++rh)
                        g_tmin[base + mi * 16 + rh * 8 + g] = vmin[h][mi][rh];
            }
        }
        __syncthreads();
    }
}

// ---------------------------------------------------------------------------
// Kernel 3: rescore (identical to R16 except the tile->code map: a 32-tile is
// item*192 + sub*32 with sub = t32 % 6).
// ---------------------------------------------------------------------------
__device__ __forceinline__ void exact_dot_update(
    const float* __restrict__ emb, const float* zr, float zn, int code,
    unsigned long long* bslot)
{
    const float4* ep = reinterpret_cast<const float4*>(emb + (size_t)code * DIM);
    float acc = 0.f;
    #pragma unroll 9
    for (int c4 = 0; c4 < 36; ++c4) {
        float4 e4 = ep[c4];
        acc = __fmaf_rn(zr[4 * c4 + 0], e4.x, acc);
        acc = __fmaf_rn(zr[4 * c4 + 1], e4.y, acc);
        acc = __fmaf_rn(zr[4 * c4 + 2], e4.z, acc);
        acc = __fmaf_rn(zr[4 * c4 + 3], e4.w, acc);
    }
    float t1v = __fadd_rn(zn, g_en[code]);
    float dd  = __fmaf_rn(acc, -2.f, t1v);
    unsigned long long key =
        ((unsigned long long)__float_as_uint(dd) << 32) | (unsigned)code;
    atomicMin(bslot, key);
}

__global__ void __launch_bounds__(128) rescore_kernel(const float* __restrict__ z,
                                                      const float* __restrict__ emb,
                                                      float* __restrict__ out)
{
    __shared__ float  zs[RRB * DIM];
    __shared__ float  warpmin[4][RRB];
    __shared__ float  tau[RRB];
    __shared__ float  znsh[RRB];
    __shared__ int    list[CAP];
    __shared__ int    cnt, ovf;
    __shared__ unsigned long long best[RRB];
    __shared__ double dsum[128];
    __shared__ int    amLast;

    const int tid  = threadIdx.x;
    const int lane = tid & 31;
    const int w    = tid >> 5;
    const int rowbase = blockIdx.x * RRB;

    for (int i = tid; i < RRB * DIM; i += 128)
        zs[i] = z[(size_t)rowbase * DIM + i];
    if (tid < RRB) { znsh[tid] = g_zn[rowbase + tid]; best[tid] = ~0ULL; }
    if (tid == 0) { cnt = 0; ovf = 0; }
    __syncthreads();

    const int TPW = NT32 / 4;   // 393
    {
        float m0 = CUDART_INF_F, m1 = CUDART_INF_F;
        const float* base = g_tmin + rowbase + lane;
        const int t0 = w * TPW;
        #pragma unroll 4
        for (int t = t0; t + 1 < t0 + TPW; t += 2) {
            m0 = fminf(m0, base[(size_t)t * N_ROWS]);
            m1 = fminf(m1, base[(size_t)(t + 1) * N_ROWS]);
        }
        m0 = fminf(m0, base[(size_t)(t0 + TPW - 1) * N_ROWS]);
        warpmin[w][lane] = fminf(m0, m1);
    }
    __syncthreads();
    if (tid < RRB) {
        float m = fminf(fminf(warpmin[0][tid], warpmin[1][tid]),
                        fminf(warpmin[2][tid], warpmin[3][tid]));
        tau[tid] = m + 4e-5f + 4e-6f * sqrtf(znsh[tid]);
    }
    __syncthreads();

    {
        const float* base = g_tmin + rowbase + lane;
        const float mytau = tau[lane];
        const int t0 = w * TPW;
        for (int t = t0; t < t0 + TPW; ++t) {
            float v = base[(size_t)t * N_ROWS];
            if (v <= mytau) {
                int k = atomicAdd(&cnt, 1);
                if (k < CAP) list[k] = (t << 5) | lane;
                else ovf = 1;
            }
        }
    }
    __syncthreads();
    const int nc = min(cnt, CAP);

    for (int v = tid; v < nc * 32; v += 128) {
        const int e    = list[v >> 5];
        const int off  = v & 31;
        const int rloc = e & 31;
        const int t32  = e >> 5;
        const int code = (t32 / 6) * 192 + (t32 % 6) * 32 + off;
        if (code < KCODES)
            exact_dot_update(emb, zs + rloc * DIM, znsh[rloc], code, &best[rloc]);
    }
    if (ovf) {
        for (int vv = tid; vv < NT32 * RRB; vv += 128) {
            const int t32 = vv >> 5, rloc = vv & 31;
            float val = g_tmin[(size_t)t32 * N_ROWS + rowbase + rloc];
            if (val <= tau[rloc]) {
                const int cb = (t32 / 6) * 192 + (t32 % 6) * 32;
                for (int off = 0; off < 32; ++off)
                    if (cb + off < KCODES)
                        exact_dot_update(emb, zs + rloc * DIM, znsh[rloc],
                                         cb + off, &best[rloc]);
            }
        }
    }
    __syncthreads();

    if (tid < RRB)
        out[ZQ_ELEMS + rowbase + tid] = (float)(int)(best[tid] & 0xffffffffu);
    {
        const int rloc = tid >> 2, qd = tid & 3;
        const int code = (int)(best[rloc] & 0xffffffffu);
        const float* ep = emb + (size_t)code * DIM;
        double ls = 0.0;
        #pragma unroll 9
        for (int d = qd * 36; d < qd * 36 + 36; ++d) {
            float e = ep[d];
            out[(size_t)(rowbase + rloc) * DIM + d] = e;
            float dx = e - zs[rloc * DIM + d];
            ls += (double)dx * dx;
        }
        dsum[tid] = ls;
    }
    __syncthreads();
    for (int s = 64; s > 0; s >>= 1) {
        if (tid < s) dsum[tid] += dsum[tid + s];
        __syncthreads();
    }
    if (tid == 0) g_blockloss[blockIdx.x] = dsum[0];
    __threadfence();
    if (tid == 0) amLast = (atomicAdd(&g_rs_cnt, 1) == RBLK - 1);
    __syncthreads();
    if (amLast) {
        dsum[tid] = g_blockloss[tid];
        __syncthreads();
        for (int s = 64; s > 0; s >>= 1) {
            if (tid < s) dsum[tid] += dsum[tid + s];
            __syncthreads();
        }
        if (tid == 0) {
            out[ZQ_ELEMS + N_ROWS] = (float)(dsum[0] / (double)ZQ_ELEMS);
            g_rs_cnt = 0;
        }
    }
}

// ---------------------------------------------------------------------------
extern "C" void kernel_launch(void* const* d_in, const int* in_sizes, int n_in,
                              void* d_out, int out_size)
{
    const float* z = nullptr;
    const float* emb = nullptr;
    for (int i = 0; i < n_in; ++i) {
        if (in_sizes[i] == N_ROWS * DIM)      z = (const float*)d_in[i];
        else if (in_sizes[i] == KCODES * DIM) emb = (const float*)d_in[i];
    }
    float* out = (float*)d_out;
    (void)out_size;

    cudaFuncSetAttribute(gemm_kernel,
                         cudaFuncAttributeMaxDynamicSharedMemorySize, SMEM_GM);

    prep_kernel<<<PBLOCKS, 256>>>(z, emb);
    gemm_kernel<<<NBLK, 256, SMEM_GM>>>();
    rescore_kernel<<<RBLK, 128>>>(z, emb, out);
}